// round 1
// baseline (speedup 1.0000x reference)
#include <cuda_runtime.h>
#include <cuda_bf16.h>

#define Bsz 8
#define Ssz 1024
#define Esz 768
#define Hsz 12
#define Dsz 64
#define Msz (Bsz*Ssz)   // 8192

// ---------------- scratch (device globals; no allocation) ----------------
__device__ float g_q[Bsz*Hsz*Ssz*Dsz];     // [B,H,S,D]
__device__ float g_k[Bsz*Hsz*Ssz*Dsz];
__device__ float g_v[Bsz*Hsz*Ssz*Dsz];
__device__ float g_attn[Bsz*Ssz*Esz];      // [B,S,E] concat-heads

// ---------------- QKV projection GEMM ----------------
// C[M=8192, N=768] = X[M,768] * W[h,e,d] + bias ; one 64x64 tile per block,
// blockIdx.z in {0,1,2} selects q/k/v. Each N-tile == one head (DH=64).
__global__ __launch_bounds__(256) void qkv_gemm(
    const float* __restrict__ X,
    const float* __restrict__ Wq, const float* __restrict__ bq,
    const float* __restrict__ Wk, const float* __restrict__ bk,
    const float* __restrict__ Wv, const float* __restrict__ bv)
{
    const int which = blockIdx.z;
    const float* W    = (which == 0) ? Wq : (which == 1 ? Wk : Wv);
    const float* bias = (which == 0) ? bq : (which == 1 ? bk : bv);
    float* OUT        = (which == 0) ? g_q : (which == 1 ? g_k : g_v);

    const int n0 = blockIdx.x * 64;        // head h = n0/64
    const int m0 = blockIdx.y * 64;
    const int h  = n0 >> 6;

    __shared__ float Asm[16][65];          // [k][m], padded
    __shared__ float Bsm[16][64];          // [k][n]

    const int t  = threadIdx.x;            // 0..255
    const int tx = t & 15;                 // n-tile 0..15
    const int ty = t >> 4;                 // m-tile 0..15

    float c[4][4];
    #pragma unroll
    for (int i = 0; i < 4; i++)
        #pragma unroll
        for (int j = 0; j < 4; j++) c[i][j] = 0.f;

    const float* Wh = W + h * (Esz * Dsz); // [E,64] for this head

    for (int k0 = 0; k0 < Esz; k0 += 16) {
        // A tile: 64 rows x 16 k. thread t -> row t/4, kq (t%4)*4, float4
        {
            int row = t >> 2, kq = (t & 3) << 2;
            float4 a4 = *(const float4*)(X + (m0 + row) * Esz + k0 + kq);
            Asm[kq + 0][row] = a4.x;
            Asm[kq + 1][row] = a4.y;
            Asm[kq + 2][row] = a4.z;
            Asm[kq + 3][row] = a4.w;
        }
        // B tile: 16 k x 64 n. thread t -> e=t/16, d=(t%16)*4
        {
            int e = t >> 4, d = (t & 15) << 2;
            float4 b4 = *(const float4*)(Wh + (k0 + e) * Dsz + d);
            *(float4*)(&Bsm[e][d]) = b4;
        }
        __syncthreads();

        #pragma unroll
        for (int kk = 0; kk < 16; kk++) {
            float a0 = Asm[kk][ty * 4 + 0];
            float a1 = Asm[kk][ty * 4 + 1];
            float a2 = Asm[kk][ty * 4 + 2];
            float a3 = Asm[kk][ty * 4 + 3];
            float4 b4 = *(float4*)(&Bsm[kk][tx * 4]);
            c[0][0] += a0 * b4.x; c[0][1] += a0 * b4.y; c[0][2] += a0 * b4.z; c[0][3] += a0 * b4.w;
            c[1][0] += a1 * b4.x; c[1][1] += a1 * b4.y; c[1][2] += a1 * b4.z; c[1][3] += a1 * b4.w;
            c[2][0] += a2 * b4.x; c[2][1] += a2 * b4.y; c[2][2] += a2 * b4.z; c[2][3] += a2 * b4.w;
            c[3][0] += a3 * b4.x; c[3][1] += a3 * b4.y; c[3][2] += a3 * b4.z; c[3][3] += a3 * b4.w;
        }
        __syncthreads();
    }

    float4 bb = *(const float4*)(bias + n0 + tx * 4);
    #pragma unroll
    for (int i = 0; i < 4; i++) {
        int mrow = m0 + ty * 4 + i;
        int b = mrow >> 10, s = mrow & 1023;
        float* op = OUT + (((b * Hsz + h) << 10) + s) * Dsz + (tx << 2);
        float4 w;
        w.x = c[i][0] + bb.x;
        w.y = c[i][1] + bb.y;
        w.z = c[i][2] + bb.z;
        w.w = c[i][3] + bb.w;
        *(float4*)op = w;
    }
}

// ---------------- flash attention ----------------
// grid: (S/64, B*H). 64 threads, one query row each. Br=Bc=64.
__global__ __launch_bounds__(64) void attn_kernel()
{
    const int bh = blockIdx.y;             // 0..95
    const int b = bh / Hsz, h = bh % Hsz;
    const int tid = threadIdx.x;
    const int r = blockIdx.x * 64 + tid;   // query row

    __shared__ float Ksm[64][64];
    __shared__ float Vsm[64][64];
    __shared__ float Ssm[64 * 64];         // [j][tid] column-major: per-thread private column

    const float* qptr = g_q + (bh * Ssz + r) * Dsz;
    float qreg[Dsz];
    #pragma unroll
    for (int d = 0; d < Dsz; d += 4) {
        float4 qv = *(const float4*)(qptr + d);
        qreg[d + 0] = qv.x * 0.125f;       // scale = 1/sqrt(64)
        qreg[d + 1] = qv.y * 0.125f;
        qreg[d + 2] = qv.z * 0.125f;
        qreg[d + 3] = qv.w * 0.125f;
    }

    float mrun = -1e30f, lrun = 0.f;
    float o[Dsz];
    #pragma unroll
    for (int d = 0; d < Dsz; d++) o[d] = 0.f;

    const float* Kbase = g_k + bh * (Ssz * Dsz);
    const float* Vbase = g_v + bh * (Ssz * Dsz);

    for (int kb = 0; kb < Ssz / 64; kb++) {
        const float4* Kt = (const float4*)(Kbase + kb * 64 * Dsz);
        const float4* Vt = (const float4*)(Vbase + kb * 64 * Dsz);
        #pragma unroll
        for (int i = 0; i < 16; i++) {
            int idx = i * 64 + tid;        // 1024 float4s per tile
            ((float4*)Ksm)[idx] = Kt[idx];
            ((float4*)Vsm)[idx] = Vt[idx];
        }
        __syncthreads();

        // pass 1: scores + tile max
        float tmax = -1e30f;
        for (int j = 0; j < 64; j++) {
            const float4* kj4 = (const float4*)(&Ksm[j][0]);
            float acc0 = 0.f, acc1 = 0.f, acc2 = 0.f, acc3 = 0.f;
            #pragma unroll
            for (int d4 = 0; d4 < 16; d4++) {
                float4 kv = kj4[d4];
                acc0 += qreg[d4 * 4 + 0] * kv.x;
                acc1 += qreg[d4 * 4 + 1] * kv.y;
                acc2 += qreg[d4 * 4 + 2] * kv.z;
                acc3 += qreg[d4 * 4 + 3] * kv.w;
            }
            float sc = (acc0 + acc1) + (acc2 + acc3);
            Ssm[j * 64 + tid] = sc;
            tmax = fmaxf(tmax, sc);
        }

        float mnew = fmaxf(mrun, tmax);
        float alpha = __expf(mrun - mnew);
        lrun *= alpha;
        #pragma unroll
        for (int d = 0; d < Dsz; d++) o[d] *= alpha;

        // pass 2: exp + PV accumulate
        for (int j = 0; j < 64; j++) {
            float p = __expf(Ssm[j * 64 + tid] - mnew);
            lrun += p;
            const float4* vj4 = (const float4*)(&Vsm[j][0]);
            #pragma unroll
            for (int d4 = 0; d4 < 16; d4++) {
                float4 vv = vj4[d4];
                o[d4 * 4 + 0] += p * vv.x;
                o[d4 * 4 + 1] += p * vv.y;
                o[d4 * 4 + 2] += p * vv.z;
                o[d4 * 4 + 3] += p * vv.w;
            }
        }
        mrun = mnew;
        __syncthreads();                   // before tile overwrite
    }

    float inv = 1.f / lrun;
    float* outp = g_attn + (b * Ssz + r) * Esz + h * Dsz;
    #pragma unroll
    for (int d = 0; d < Dsz; d += 4) {
        float4 w;
        w.x = o[d + 0] * inv;
        w.y = o[d + 1] * inv;
        w.z = o[d + 2] * inv;
        w.w = o[d + 3] * inv;
        *(float4*)(outp + d) = w;
    }
}

// ---------------- output projection GEMM ----------------
__global__ __launch_bounds__(256) void oproj_gemm(
    const float* __restrict__ Wo, const float* __restrict__ bo,
    float* __restrict__ out)
{
    const int n0 = blockIdx.x * 64;
    const int m0 = blockIdx.y * 64;

    __shared__ float Asm[16][65];
    __shared__ float Bsm[16][64];

    const int t  = threadIdx.x;
    const int tx = t & 15;
    const int ty = t >> 4;

    float c[4][4];
    #pragma unroll
    for (int i = 0; i < 4; i++)
        #pragma unroll
        for (int j = 0; j < 4; j++) c[i][j] = 0.f;

    for (int k0 = 0; k0 < Esz; k0 += 16) {
        {
            int row = t >> 2, kq = (t & 3) << 2;
            float4 a4 = *(const float4*)(g_attn + (m0 + row) * Esz + k0 + kq);
            Asm[kq + 0][row] = a4.x;
            Asm[kq + 1][row] = a4.y;
            Asm[kq + 2][row] = a4.z;
            Asm[kq + 3][row] = a4.w;
        }
        {
            int e = t >> 4, d = (t & 15) << 2;
            float4 b4 = *(const float4*)(Wo + (k0 + e) * Esz + n0 + d);
            *(float4*)(&Bsm[e][d]) = b4;
        }
        __syncthreads();

        #pragma unroll
        for (int kk = 0; kk < 16; kk++) {
            float a0 = Asm[kk][ty * 4 + 0];
            float a1 = Asm[kk][ty * 4 + 1];
            float a2 = Asm[kk][ty * 4 + 2];
            float a3 = Asm[kk][ty * 4 + 3];
            float4 b4 = *(float4*)(&Bsm[kk][tx * 4]);
            c[0][0] += a0 * b4.x; c[0][1] += a0 * b4.y; c[0][2] += a0 * b4.z; c[0][3] += a0 * b4.w;
            c[1][0] += a1 * b4.x; c[1][1] += a1 * b4.y; c[1][2] += a1 * b4.z; c[1][3] += a1 * b4.w;
            c[2][0] += a2 * b4.x; c[2][1] += a2 * b4.y; c[2][2] += a2 * b4.z; c[2][3] += a2 * b4.w;
            c[3][0] += a3 * b4.x; c[3][1] += a3 * b4.y; c[3][2] += a3 * b4.z; c[3][3] += a3 * b4.w;
        }
        __syncthreads();
    }

    float4 bb = *(const float4*)(bo + n0 + tx * 4);
    #pragma unroll
    for (int i = 0; i < 4; i++) {
        int mrow = m0 + ty * 4 + i;
        float* op = out + mrow * Esz + n0 + (tx << 2);
        float4 w;
        w.x = c[i][0] + bb.x;
        w.y = c[i][1] + bb.y;
        w.z = c[i][2] + bb.z;
        w.w = c[i][3] + bb.w;
        *(float4*)op = w;
    }
}

// ---------------- launch ----------------
extern "C" void kernel_launch(void* const* d_in, const int* in_sizes, int n_in,
                              void* d_out, int out_size)
{
    const float* X  = (const float*)d_in[0];
    const float* Wq = (const float*)d_in[1];
    const float* bq = (const float*)d_in[2];
    const float* Wk = (const float*)d_in[3];
    const float* bk = (const float*)d_in[4];
    const float* Wv = (const float*)d_in[5];
    const float* bv = (const float*)d_in[6];
    const float* Wo = (const float*)d_in[7];
    const float* bo = (const float*)d_in[8];
    float* out = (float*)d_out;

    dim3 g1(Esz / 64, Msz / 64, 3);        // (12, 128, 3)
    qkv_gemm<<<g1, 256>>>(X, Wq, bq, Wk, bk, Wv, bv);

    dim3 g2(Ssz / 64, Bsz * Hsz);          // (16, 96)
    attn_kernel<<<g2, 64>>>();

    dim3 g3(Esz / 64, Msz / 64);           // (12, 128)
    oproj_gemm<<<g3, 256>>>(Wo, bo, out);
}

// round 2
// speedup vs baseline: 1.1417x; 1.1417x over previous
#include <cuda_runtime.h>
#include <cuda_bf16.h>

#define Bsz 8
#define Ssz 1024
#define Esz 768
#define Hsz 12
#define Dsz 64
#define Msz (Bsz*Ssz)   // 8192

// ---------------- scratch (device globals; no allocation) ----------------
__device__ float g_q[Bsz*Hsz*Ssz*Dsz];     // [B,H,S,D]
__device__ float g_k[Bsz*Hsz*Ssz*Dsz];
__device__ float g_v[Bsz*Hsz*Ssz*Dsz];
__device__ float g_attn[Bsz*Ssz*Esz];      // [B,S,E] concat-heads

// ============================================================================
// QKV projection GEMM: 128(M) x 64(N=head) tile, Kc=16, double-buffered smem,
// 256 threads, 8x4 micro-tile. blockIdx.z selects q/k/v; blockIdx.x = head.
// ============================================================================
__global__ __launch_bounds__(256) void qkv_gemm(
    const float* __restrict__ X,
    const float* __restrict__ Wq, const float* __restrict__ bq,
    const float* __restrict__ Wk, const float* __restrict__ bk,
    const float* __restrict__ Wv, const float* __restrict__ bv)
{
    const int which = blockIdx.z;
    const float* W    = (which == 0) ? Wq : (which == 1 ? Wk : Wv);
    const float* bias = (which == 0) ? bq : (which == 1 ? bk : bv);
    float* OUT        = (which == 0) ? g_q : (which == 1 ? g_k : g_v);

    const int h  = blockIdx.x;             // head
    const int m0 = blockIdx.y * 128;

    __shared__ float As[2][16][136];       // [buf][k][m] padded
    __shared__ float Bs[2][16][64];        // [buf][k][n]

    const int t  = threadIdx.x;
    const int tx = t & 15;                 // n micro 0..15 (4 cols each)
    const int ty = t >> 4;                 // m micro 0..15 (8 rows each)

    // global-load mapping
    const int arow = t >> 1;               // 0..127
    const int akq  = (t & 1) << 3;         // 0 or 8
    const float* Aptr = X + (m0 + arow) * Esz + akq;
    const float* Wh   = W + h * (Esz * Dsz);
    const int be = t >> 4;                 // 0..15
    const int bd = (t & 15) << 2;          // 0..60
    const float* Bptr = Wh + be * Dsz + bd;

    // prologue: load k-tile 0
    float4 pa0 = *(const float4*)(Aptr);
    float4 pa1 = *(const float4*)(Aptr + 4);
    float4 pb  = *(const float4*)(Bptr);

    As[0][akq + 0][arow] = pa0.x;
    As[0][akq + 1][arow] = pa0.y;
    As[0][akq + 2][arow] = pa0.z;
    As[0][akq + 3][arow] = pa0.w;
    As[0][akq + 4][arow] = pa1.x;
    As[0][akq + 5][arow] = pa1.y;
    As[0][akq + 6][arow] = pa1.z;
    As[0][akq + 7][arow] = pa1.w;
    *(float4*)&Bs[0][be][bd] = pb;
    __syncthreads();

    float acc[8][4];
    #pragma unroll
    for (int i = 0; i < 8; i++)
        #pragma unroll
        for (int j = 0; j < 4; j++) acc[i][j] = 0.f;

    for (int k0 = 0; k0 < Esz; k0 += 16) {
        const int buf = (k0 >> 4) & 1;
        const bool more = (k0 + 16) < Esz;
        if (more) {
            pa0 = *(const float4*)(Aptr + k0 + 16);
            pa1 = *(const float4*)(Aptr + k0 + 20);
            pb  = *(const float4*)(Bptr + (k0 + 16) * Dsz);
        }
        #pragma unroll
        for (int kk = 0; kk < 16; kk++) {
            float4 a0 = *(float4*)&As[buf][kk][ty * 8];
            float4 a1 = *(float4*)&As[buf][kk][ty * 8 + 4];
            float4 bv = *(float4*)&Bs[buf][kk][tx * 4];
            acc[0][0] += a0.x * bv.x; acc[0][1] += a0.x * bv.y; acc[0][2] += a0.x * bv.z; acc[0][3] += a0.x * bv.w;
            acc[1][0] += a0.y * bv.x; acc[1][1] += a0.y * bv.y; acc[1][2] += a0.y * bv.z; acc[1][3] += a0.y * bv.w;
            acc[2][0] += a0.z * bv.x; acc[2][1] += a0.z * bv.y; acc[2][2] += a0.z * bv.z; acc[2][3] += a0.z * bv.w;
            acc[3][0] += a0.w * bv.x; acc[3][1] += a0.w * bv.y; acc[3][2] += a0.w * bv.z; acc[3][3] += a0.w * bv.w;
            acc[4][0] += a1.x * bv.x; acc[4][1] += a1.x * bv.y; acc[4][2] += a1.x * bv.z; acc[4][3] += a1.x * bv.w;
            acc[5][0] += a1.y * bv.x; acc[5][1] += a1.y * bv.y; acc[5][2] += a1.y * bv.z; acc[5][3] += a1.y * bv.w;
            acc[6][0] += a1.z * bv.x; acc[6][1] += a1.z * bv.y; acc[6][2] += a1.z * bv.z; acc[6][3] += a1.z * bv.w;
            acc[7][0] += a1.w * bv.x; acc[7][1] += a1.w * bv.y; acc[7][2] += a1.w * bv.z; acc[7][3] += a1.w * bv.w;
        }
        if (more) {
            const int nb = buf ^ 1;
            As[nb][akq + 0][arow] = pa0.x;
            As[nb][akq + 1][arow] = pa0.y;
            As[nb][akq + 2][arow] = pa0.z;
            As[nb][akq + 3][arow] = pa0.w;
            As[nb][akq + 4][arow] = pa1.x;
            As[nb][akq + 5][arow] = pa1.y;
            As[nb][akq + 6][arow] = pa1.z;
            As[nb][akq + 7][arow] = pa1.w;
            *(float4*)&Bs[nb][be][bd] = pb;
        }
        __syncthreads();
    }

    float4 bb = *(const float4*)(bias + h * Dsz + tx * 4);
    #pragma unroll
    for (int i = 0; i < 8; i++) {
        int mrow = m0 + ty * 8 + i;
        int b = mrow >> 10, s = mrow & 1023;
        float4 w;
        w.x = acc[i][0] + bb.x;
        w.y = acc[i][1] + bb.y;
        w.z = acc[i][2] + bb.z;
        w.w = acc[i][3] + bb.w;
        *(float4*)(OUT + (((b * Hsz + h) << 10) + s) * Dsz + (tx << 2)) = w;
    }
}

// ============================================================================
// flash attention: grid (S/64, B*H), 64 threads, one query row each.
// Kc=32 tiles (24KB smem -> 6 blocks/SM), two-pass softmax per tile, 8-acc dot.
// ============================================================================
__global__ __launch_bounds__(64) void attn_kernel()
{
    const int bh = blockIdx.y;             // 0..95
    const int b = bh / Hsz, h = bh % Hsz;
    const int tid = threadIdx.x;
    const int r = blockIdx.x * 64 + tid;

    __shared__ float Ksm[32][64];
    __shared__ float Vsm[32][64];
    __shared__ float Ssm[32 * 64];         // [j][tid] column-private

    const float* qptr = g_q + (bh * Ssz + r) * Dsz;
    float qreg[Dsz];
    #pragma unroll
    for (int d = 0; d < Dsz; d += 4) {
        float4 qv = *(const float4*)(qptr + d);
        qreg[d + 0] = qv.x * 0.125f;       // 1/sqrt(64)
        qreg[d + 1] = qv.y * 0.125f;
        qreg[d + 2] = qv.z * 0.125f;
        qreg[d + 3] = qv.w * 0.125f;
    }

    float mrun = -1e30f, lrun = 0.f;
    float o[Dsz];
    #pragma unroll
    for (int d = 0; d < Dsz; d++) o[d] = 0.f;

    const float* Kbase = g_k + bh * (Ssz * Dsz);
    const float* Vbase = g_v + bh * (Ssz * Dsz);

    for (int kb = 0; kb < Ssz / 32; kb++) {
        const float4* Kt = (const float4*)(Kbase + kb * 32 * Dsz);
        const float4* Vt = (const float4*)(Vbase + kb * 32 * Dsz);
        #pragma unroll
        for (int i = 0; i < 8; i++) {
            int idx = i * 64 + tid;        // 512 float4 per tile
            ((float4*)Ksm)[idx] = Kt[idx];
            ((float4*)Vsm)[idx] = Vt[idx];
        }
        __syncthreads();

        // pass 1: scores + tile max (8 independent accumulators)
        float tmax = -1e30f;
        #pragma unroll 2
        for (int j = 0; j < 32; j++) {
            const float4* kj4 = (const float4*)(&Ksm[j][0]);
            float s0 = 0.f, s1 = 0.f, s2 = 0.f, s3 = 0.f;
            float s4 = 0.f, s5 = 0.f, s6 = 0.f, s7 = 0.f;
            #pragma unroll
            for (int d8 = 0; d8 < 8; d8++) {
                float4 k0 = kj4[d8 * 2];
                float4 k1 = kj4[d8 * 2 + 1];
                s0 += qreg[d8 * 8 + 0] * k0.x;
                s1 += qreg[d8 * 8 + 1] * k0.y;
                s2 += qreg[d8 * 8 + 2] * k0.z;
                s3 += qreg[d8 * 8 + 3] * k0.w;
                s4 += qreg[d8 * 8 + 4] * k1.x;
                s5 += qreg[d8 * 8 + 5] * k1.y;
                s6 += qreg[d8 * 8 + 6] * k1.z;
                s7 += qreg[d8 * 8 + 7] * k1.w;
            }
            float sc = ((s0 + s1) + (s2 + s3)) + ((s4 + s5) + (s6 + s7));
            Ssm[j * 64 + tid] = sc;
            tmax = fmaxf(tmax, sc);
        }

        float mnew = fmaxf(mrun, tmax);
        float alpha = __expf(mrun - mnew);
        lrun *= alpha;
        #pragma unroll
        for (int d = 0; d < Dsz; d++) o[d] *= alpha;

        // pass 2: exp + PV accumulate
        #pragma unroll 2
        for (int j = 0; j < 32; j++) {
            float p = __expf(Ssm[j * 64 + tid] - mnew);
            lrun += p;
            const float4* vj4 = (const float4*)(&Vsm[j][0]);
            #pragma unroll
            for (int d4 = 0; d4 < 16; d4++) {
                float4 vv = vj4[d4];
                o[d4 * 4 + 0] += p * vv.x;
                o[d4 * 4 + 1] += p * vv.y;
                o[d4 * 4 + 2] += p * vv.z;
                o[d4 * 4 + 3] += p * vv.w;
            }
        }
        mrun = mnew;
        __syncthreads();
    }

    float inv = 1.f / lrun;
    float* outp = g_attn + (b * Ssz + r) * Esz + h * Dsz;
    #pragma unroll
    for (int d = 0; d < Dsz; d += 4) {
        float4 w;
        w.x = o[d + 0] * inv;
        w.y = o[d + 1] * inv;
        w.z = o[d + 2] * inv;
        w.w = o[d + 3] * inv;
        *(float4*)(outp + d) = w;
    }
}

// ============================================================================
// output projection GEMM: same 128x64 double-buffered scheme, B = Wo[768,768]
// ============================================================================
__global__ __launch_bounds__(256) void oproj_gemm(
    const float* __restrict__ Wo, const float* __restrict__ bo,
    float* __restrict__ out)
{
    const int n0 = blockIdx.x * 64;
    const int m0 = blockIdx.y * 128;

    __shared__ float As[2][16][136];
    __shared__ float Bs[2][16][64];

    const int t  = threadIdx.x;
    const int tx = t & 15;
    const int ty = t >> 4;

    const int arow = t >> 1;
    const int akq  = (t & 1) << 3;
    const float* Aptr = g_attn + (m0 + arow) * Esz + akq;
    const int be = t >> 4;
    const int bd = (t & 15) << 2;
    const float* Bptr = Wo + be * Esz + n0 + bd;

    float4 pa0 = *(const float4*)(Aptr);
    float4 pa1 = *(const float4*)(Aptr + 4);
    float4 pb  = *(const float4*)(Bptr);

    As[0][akq + 0][arow] = pa0.x;
    As[0][akq + 1][arow] = pa0.y;
    As[0][akq + 2][arow] = pa0.z;
    As[0][akq + 3][arow] = pa0.w;
    As[0][akq + 4][arow] = pa1.x;
    As[0][akq + 5][arow] = pa1.y;
    As[0][akq + 6][arow] = pa1.z;
    As[0][akq + 7][arow] = pa1.w;
    *(float4*)&Bs[0][be][bd] = pb;
    __syncthreads();

    float acc[8][4];
    #pragma unroll
    for (int i = 0; i < 8; i++)
        #pragma unroll
        for (int j = 0; j < 4; j++) acc[i][j] = 0.f;

    for (int k0 = 0; k0 < Esz; k0 += 16) {
        const int buf = (k0 >> 4) & 1;
        const bool more = (k0 + 16) < Esz;
        if (more) {
            pa0 = *(const float4*)(Aptr + k0 + 16);
            pa1 = *(const float4*)(Aptr + k0 + 20);
            pb  = *(const float4*)(Bptr + (k0 + 16) * Esz);
        }
        #pragma unroll
        for (int kk = 0; kk < 16; kk++) {
            float4 a0 = *(float4*)&As[buf][kk][ty * 8];
            float4 a1 = *(float4*)&As[buf][kk][ty * 8 + 4];
            float4 bv = *(float4*)&Bs[buf][kk][tx * 4];
            acc[0][0] += a0.x * bv.x; acc[0][1] += a0.x * bv.y; acc[0][2] += a0.x * bv.z; acc[0][3] += a0.x * bv.w;
            acc[1][0] += a0.y * bv.x; acc[1][1] += a0.y * bv.y; acc[1][2] += a0.y * bv.z; acc[1][3] += a0.y * bv.w;
            acc[2][0] += a0.z * bv.x; acc[2][1] += a0.z * bv.y; acc[2][2] += a0.z * bv.z; acc[2][3] += a0.z * bv.w;
            acc[3][0] += a0.w * bv.x; acc[3][1] += a0.w * bv.y; acc[3][2] += a0.w * bv.z; acc[3][3] += a0.w * bv.w;
            acc[4][0] += a1.x * bv.x; acc[4][1] += a1.x * bv.y; acc[4][2] += a1.x * bv.z; acc[4][3] += a1.x * bv.w;
            acc[5][0] += a1.y * bv.x; acc[5][1] += a1.y * bv.y; acc[5][2] += a1.y * bv.z; acc[5][3] += a1.y * bv.w;
            acc[6][0] += a1.z * bv.x; acc[6][1] += a1.z * bv.y; acc[6][2] += a1.z * bv.z; acc[6][3] += a1.z * bv.w;
            acc[7][0] += a1.w * bv.x; acc[7][1] += a1.w * bv.y; acc[7][2] += a1.w * bv.z; acc[7][3] += a1.w * bv.w;
        }
        if (more) {
            const int nb = buf ^ 1;
            As[nb][akq + 0][arow] = pa0.x;
            As[nb][akq + 1][arow] = pa0.y;
            As[nb][akq + 2][arow] = pa0.z;
            As[nb][akq + 3][arow] = pa0.w;
            As[nb][akq + 4][arow] = pa1.x;
            As[nb][akq + 5][arow] = pa1.y;
            As[nb][akq + 6][arow] = pa1.z;
            As[nb][akq + 7][arow] = pa1.w;
            *(float4*)&Bs[nb][be][bd] = pb;
        }
        __syncthreads();
    }

    float4 bb = *(const float4*)(bo + n0 + tx * 4);
    #pragma unroll
    for (int i = 0; i < 8; i++) {
        int mrow = m0 + ty * 8 + i;
        float4 w;
        w.x = acc[i][0] + bb.x;
        w.y = acc[i][1] + bb.y;
        w.z = acc[i][2] + bb.z;
        w.w = acc[i][3] + bb.w;
        *(float4*)(out + mrow * Esz + n0 + (tx << 2)) = w;
    }
}

// ---------------- launch ----------------
extern "C" void kernel_launch(void* const* d_in, const int* in_sizes, int n_in,
                              void* d_out, int out_size)
{
    const float* X  = (const float*)d_in[0];
    const float* Wq = (const float*)d_in[1];
    const float* bq = (const float*)d_in[2];
    const float* Wk = (const float*)d_in[3];
    const float* bk = (const float*)d_in[4];
    const float* Wv = (const float*)d_in[5];
    const float* bv = (const float*)d_in[6];
    const float* Wo = (const float*)d_in[7];
    const float* bo = (const float*)d_in[8];
    float* out = (float*)d_out;

    dim3 g1(Hsz, Msz / 128, 3);            // (12, 64, 3)
    qkv_gemm<<<g1, 256>>>(X, Wq, bq, Wk, bk, Wv, bv);

    dim3 g2(Ssz / 64, Bsz * Hsz);          // (16, 96)
    attn_kernel<<<g2, 64>>>();

    dim3 g3(Esz / 64, Msz / 128);          // (12, 64)
    oproj_gemm<<<g3, 256>>>(Wo, bo, out);
}

// round 3
// speedup vs baseline: 1.9191x; 1.6809x over previous
#include <cuda_runtime.h>
#include <cuda_bf16.h>

#define Bsz 8
#define Ssz 1024
#define Esz 768
#define Hsz 12
#define Dsz 64
#define Msz (Bsz*Ssz)   // 8192

// ---------------- scratch (device globals; no allocation) ----------------
__device__ float g_q[Bsz*Hsz*Ssz*Dsz];     // [B,H,S,D]
__device__ float g_k[Bsz*Hsz*Ssz*Dsz];
__device__ float g_v[Bsz*Hsz*Ssz*Dsz];
__device__ float g_attn[Bsz*Ssz*Esz];      // [B,S,E] concat-heads

// ---------------- tf32 helpers ----------------
__device__ __forceinline__ unsigned f2tf(float f) {
    unsigned u;
    asm("cvt.rna.tf32.f32 %0, %1;" : "=r"(u) : "f"(f));
    return u;
}
__device__ __forceinline__ void mma_tf32(float* c, const unsigned* a, unsigned b0, unsigned b1) {
    asm volatile(
        "mma.sync.aligned.m16n8k8.row.col.f32.tf32.tf32.f32 "
        "{%0,%1,%2,%3}, {%4,%5,%6,%7}, {%8,%9}, {%0,%1,%2,%3};"
        : "+f"(c[0]), "+f"(c[1]), "+f"(c[2]), "+f"(c[3])
        : "r"(a[0]), "r"(a[1]), "r"(a[2]), "r"(a[3]), "r"(b0), "r"(b1));
}

// ============================================================================
// QKV projection GEMM (fp32 FFMA, unchanged from R2 — exact)
// ============================================================================
__global__ __launch_bounds__(256) void qkv_gemm(
    const float* __restrict__ X,
    const float* __restrict__ Wq, const float* __restrict__ bq,
    const float* __restrict__ Wk, const float* __restrict__ bk,
    const float* __restrict__ Wv, const float* __restrict__ bv)
{
    const int which = blockIdx.z;
    const float* W    = (which == 0) ? Wq : (which == 1 ? Wk : Wv);
    const float* bias = (which == 0) ? bq : (which == 1 ? bk : bv);
    float* OUT        = (which == 0) ? g_q : (which == 1 ? g_k : g_v);

    const int h  = blockIdx.x;
    const int m0 = blockIdx.y * 128;

    __shared__ float As[2][16][136];
    __shared__ float Bs[2][16][64];

    const int t  = threadIdx.x;
    const int tx = t & 15;
    const int ty = t >> 4;

    const int arow = t >> 1;
    const int akq  = (t & 1) << 3;
    const float* Aptr = X + (m0 + arow) * Esz + akq;
    const float* Wh   = W + h * (Esz * Dsz);
    const int be = t >> 4;
    const int bd = (t & 15) << 2;
    const float* Bptr = Wh + be * Dsz + bd;

    float4 pa0 = *(const float4*)(Aptr);
    float4 pa1 = *(const float4*)(Aptr + 4);
    float4 pb  = *(const float4*)(Bptr);

    As[0][akq + 0][arow] = pa0.x;
    As[0][akq + 1][arow] = pa0.y;
    As[0][akq + 2][arow] = pa0.z;
    As[0][akq + 3][arow] = pa0.w;
    As[0][akq + 4][arow] = pa1.x;
    As[0][akq + 5][arow] = pa1.y;
    As[0][akq + 6][arow] = pa1.z;
    As[0][akq + 7][arow] = pa1.w;
    *(float4*)&Bs[0][be][bd] = pb;
    __syncthreads();

    float acc[8][4];
    #pragma unroll
    for (int i = 0; i < 8; i++)
        #pragma unroll
        for (int j = 0; j < 4; j++) acc[i][j] = 0.f;

    for (int k0 = 0; k0 < Esz; k0 += 16) {
        const int buf = (k0 >> 4) & 1;
        const bool more = (k0 + 16) < Esz;
        if (more) {
            pa0 = *(const float4*)(Aptr + k0 + 16);
            pa1 = *(const float4*)(Aptr + k0 + 20);
            pb  = *(const float4*)(Bptr + (k0 + 16) * Dsz);
        }
        #pragma unroll
        for (int kk = 0; kk < 16; kk++) {
            float4 a0 = *(float4*)&As[buf][kk][ty * 8];
            float4 a1 = *(float4*)&As[buf][kk][ty * 8 + 4];
            float4 bv = *(float4*)&Bs[buf][kk][tx * 4];
            acc[0][0] += a0.x * bv.x; acc[0][1] += a0.x * bv.y; acc[0][2] += a0.x * bv.z; acc[0][3] += a0.x * bv.w;
            acc[1][0] += a0.y * bv.x; acc[1][1] += a0.y * bv.y; acc[1][2] += a0.y * bv.z; acc[1][3] += a0.y * bv.w;
            acc[2][0] += a0.z * bv.x; acc[2][1] += a0.z * bv.y; acc[2][2] += a0.z * bv.z; acc[2][3] += a0.z * bv.w;
            acc[3][0] += a0.w * bv.x; acc[3][1] += a0.w * bv.y; acc[3][2] += a0.w * bv.z; acc[3][3] += a0.w * bv.w;
            acc[4][0] += a1.x * bv.x; acc[4][1] += a1.x * bv.y; acc[4][2] += a1.x * bv.z; acc[4][3] += a1.x * bv.w;
            acc[5][0] += a1.y * bv.x; acc[5][1] += a1.y * bv.y; acc[5][2] += a1.y * bv.z; acc[5][3] += a1.y * bv.w;
            acc[6][0] += a1.z * bv.x; acc[6][1] += a1.z * bv.y; acc[6][2] += a1.z * bv.z; acc[6][3] += a1.z * bv.w;
            acc[7][0] += a1.w * bv.x; acc[7][1] += a1.w * bv.y; acc[7][2] += a1.w * bv.z; acc[7][3] += a1.w * bv.w;
        }
        if (more) {
            const int nb = buf ^ 1;
            As[nb][akq + 0][arow] = pa0.x;
            As[nb][akq + 1][arow] = pa0.y;
            As[nb][akq + 2][arow] = pa0.z;
            As[nb][akq + 3][arow] = pa0.w;
            As[nb][akq + 4][arow] = pa1.x;
            As[nb][akq + 5][arow] = pa1.y;
            As[nb][akq + 6][arow] = pa1.z;
            As[nb][akq + 7][arow] = pa1.w;
            *(float4*)&Bs[nb][be][bd] = pb;
        }
        __syncthreads();
    }

    float4 bb = *(const float4*)(bias + h * Dsz + tx * 4);
    #pragma unroll
    for (int i = 0; i < 8; i++) {
        int mrow = m0 + ty * 8 + i;
        int b = mrow >> 10, s = mrow & 1023;
        float4 w;
        w.x = acc[i][0] + bb.x;
        w.y = acc[i][1] + bb.y;
        w.z = acc[i][2] + bb.z;
        w.w = acc[i][3] + bb.w;
        *(float4*)(OUT + (((b * Hsz + h) << 10) + s) * Dsz + (tx << 2)) = w;
    }
}

// ============================================================================
// Flash attention with tf32 mma.sync.m16n8k8
// grid (S/64, B*H), 128 threads = 4 warps; warp w owns query rows 16w..16w+15.
// Ksm (stride 68) doubles as the P buffer after QK^T; Vsm stride 72.
// ============================================================================
#define KST 68
#define VST 72

__global__ __launch_bounds__(128) void attn_kernel()
{
    __shared__ unsigned Ksm[64 * KST];     // K tile (tf32) -> reused as P
    __shared__ unsigned Vsm[64 * VST];     // V tile (tf32)

    const int bh = blockIdx.y;
    const int b = bh / Hsz, h = bh % Hsz;
    const int tid  = threadIdx.x;
    const int warp = tid >> 5;
    const int lane = tid & 31;
    const int g  = lane >> 2;              // groupID 0..7
    const int tg = lane & 3;               // thread-in-group 0..3
    const int r0 = warp * 16;              // warp's query-row base in tile

    // ---- stage Q (scaled, tf32) into Ksm, extract A-frags ----
    {
        const float4* Qg = (const float4*)(g_q + (bh * Ssz + blockIdx.x * 64) * Dsz);
        #pragma unroll
        for (int i = 0; i < 8; i++) {
            int idx = i * 128 + tid;
            int row = idx >> 4, c = (idx & 15) << 2;
            float4 qv = Qg[idx];
            uint4 u;
            u.x = f2tf(qv.x * 0.125f);
            u.y = f2tf(qv.y * 0.125f);
            u.z = f2tf(qv.z * 0.125f);
            u.w = f2tf(qv.w * 0.125f);
            *(uint4*)&Ksm[row * KST + c] = u;
        }
    }
    __syncthreads();

    unsigned qa[8][4];
    #pragma unroll
    for (int kk = 0; kk < 8; kk++) {
        qa[kk][0] = Ksm[(r0 + g) * KST + kk * 8 + tg];
        qa[kk][1] = Ksm[(r0 + g + 8) * KST + kk * 8 + tg];
        qa[kk][2] = Ksm[(r0 + g) * KST + kk * 8 + tg + 4];
        qa[kk][3] = Ksm[(r0 + g + 8) * KST + kk * 8 + tg + 4];
    }
    __syncthreads();

    float o[8][4];
    #pragma unroll
    for (int nf = 0; nf < 8; nf++)
        #pragma unroll
        for (int j = 0; j < 4; j++) o[nf][j] = 0.f;
    float m_lo = -1e30f, m_hi = -1e30f, l_lo = 0.f, l_hi = 0.f;

    const float4* Kg0 = (const float4*)(g_k + bh * (Ssz * Dsz));
    const float4* Vg0 = (const float4*)(g_v + bh * (Ssz * Dsz));

    for (int kb = 0; kb < Ssz / 64; kb++) {
        // ---- load K,V tile (cvt to tf32 at store) ----
        const float4* Kg = Kg0 + kb * 1024;
        const float4* Vg = Vg0 + kb * 1024;
        #pragma unroll
        for (int i = 0; i < 8; i++) {
            int idx = i * 128 + tid;
            int row = idx >> 4, c = (idx & 15) << 2;
            float4 kv = Kg[idx];
            uint4 uk;
            uk.x = f2tf(kv.x); uk.y = f2tf(kv.y); uk.z = f2tf(kv.z); uk.w = f2tf(kv.w);
            *(uint4*)&Ksm[row * KST + c] = uk;
            float4 vv = Vg[idx];
            uint4 uv;
            uv.x = f2tf(vv.x); uv.y = f2tf(vv.y); uv.z = f2tf(vv.z); uv.w = f2tf(vv.w);
            *(uint4*)&Vsm[row * VST + c] = uv;
        }
        __syncthreads();

        // ---- S = Q K^T (tf32 mma) ----
        float s[8][4];
        #pragma unroll
        for (int nf = 0; nf < 8; nf++)
            #pragma unroll
            for (int j = 0; j < 4; j++) s[nf][j] = 0.f;

        #pragma unroll
        for (int nf = 0; nf < 8; nf++) {
            const int jrow = (nf * 8 + g) * KST;
            #pragma unroll
            for (int kk = 0; kk < 8; kk++) {
                unsigned b0 = Ksm[jrow + kk * 8 + tg];
                unsigned b1 = Ksm[jrow + kk * 8 + tg + 4];
                mma_tf32(s[nf], qa[kk], b0, b1);
            }
        }
        __syncthreads();                   // all warps done reading K

        // ---- online softmax (rows g -> lo, g+8 -> hi) ----
        float tmax_lo = -1e30f, tmax_hi = -1e30f;
        #pragma unroll
        for (int nf = 0; nf < 8; nf++) {
            tmax_lo = fmaxf(tmax_lo, fmaxf(s[nf][0], s[nf][1]));
            tmax_hi = fmaxf(tmax_hi, fmaxf(s[nf][2], s[nf][3]));
        }
        tmax_lo = fmaxf(tmax_lo, __shfl_xor_sync(0xffffffffu, tmax_lo, 1));
        tmax_lo = fmaxf(tmax_lo, __shfl_xor_sync(0xffffffffu, tmax_lo, 2));
        tmax_hi = fmaxf(tmax_hi, __shfl_xor_sync(0xffffffffu, tmax_hi, 1));
        tmax_hi = fmaxf(tmax_hi, __shfl_xor_sync(0xffffffffu, tmax_hi, 2));

        float mn_lo = fmaxf(m_lo, tmax_lo);
        float mn_hi = fmaxf(m_hi, tmax_hi);
        float a_lo = __expf(m_lo - mn_lo);
        float a_hi = __expf(m_hi - mn_hi);

        float sum_lo = 0.f, sum_hi = 0.f;
        #pragma unroll
        for (int nf = 0; nf < 8; nf++) {
            float p0 = __expf(s[nf][0] - mn_lo);
            float p1 = __expf(s[nf][1] - mn_lo);
            float p2 = __expf(s[nf][2] - mn_hi);
            float p3 = __expf(s[nf][3] - mn_hi);
            sum_lo += p0 + p1;
            sum_hi += p2 + p3;
            // write P (tf32) into Ksm
            uint2 plo, phi;
            plo.x = f2tf(p0); plo.y = f2tf(p1);
            phi.x = f2tf(p2); phi.y = f2tf(p3);
            *(uint2*)&Ksm[(r0 + g) * KST + nf * 8 + 2 * tg]     = plo;
            *(uint2*)&Ksm[(r0 + g + 8) * KST + nf * 8 + 2 * tg] = phi;
            o[nf][0] *= a_lo; o[nf][1] *= a_lo;
            o[nf][2] *= a_hi; o[nf][3] *= a_hi;
        }
        sum_lo += __shfl_xor_sync(0xffffffffu, sum_lo, 1);
        sum_lo += __shfl_xor_sync(0xffffffffu, sum_lo, 2);
        sum_hi += __shfl_xor_sync(0xffffffffu, sum_hi, 1);
        sum_hi += __shfl_xor_sync(0xffffffffu, sum_hi, 2);
        l_lo = l_lo * a_lo + sum_lo;
        l_hi = l_hi * a_hi + sum_hi;
        m_lo = mn_lo; m_hi = mn_hi;
        __syncwarp();                      // P visible within warp

        // ---- O += P V (tf32 mma) ----
        #pragma unroll
        for (int kk = 0; kk < 8; kk++) {
            unsigned pa[4];
            pa[0] = Ksm[(r0 + g) * KST + kk * 8 + tg];
            pa[1] = Ksm[(r0 + g + 8) * KST + kk * 8 + tg];
            pa[2] = Ksm[(r0 + g) * KST + kk * 8 + tg + 4];
            pa[3] = Ksm[(r0 + g + 8) * KST + kk * 8 + tg + 4];
            #pragma unroll
            for (int nf = 0; nf < 8; nf++) {
                unsigned b0 = Vsm[(kk * 8 + tg) * VST + nf * 8 + g];
                unsigned b1 = Vsm[(kk * 8 + tg + 4) * VST + nf * 8 + g];
                mma_tf32(o[nf], pa, b0, b1);
            }
        }
        __syncthreads();                   // done with P & V before next tile
    }

    // ---- epilogue: normalize + write concat layout ----
    float inv_lo = 1.f / l_lo;
    float inv_hi = 1.f / l_hi;
    const int qrow_lo = blockIdx.x * 64 + r0 + g;
    float* out_lo = g_attn + (b * Ssz + qrow_lo) * Esz + h * Dsz;
    float* out_hi = out_lo + 8 * Esz;
    #pragma unroll
    for (int nf = 0; nf < 8; nf++) {
        int col = nf * 8 + 2 * tg;
        float2 wlo, whi;
        wlo.x = o[nf][0] * inv_lo; wlo.y = o[nf][1] * inv_lo;
        whi.x = o[nf][2] * inv_hi; whi.y = o[nf][3] * inv_hi;
        *(float2*)(out_lo + col) = wlo;
        *(float2*)(out_hi + col) = whi;
    }
}

// ============================================================================
// output projection GEMM (fp32 FFMA, unchanged from R2 — exact)
// ============================================================================
__global__ __launch_bounds__(256) void oproj_gemm(
    const float* __restrict__ Wo, const float* __restrict__ bo,
    float* __restrict__ out)
{
    const int n0 = blockIdx.x * 64;
    const int m0 = blockIdx.y * 128;

    __shared__ float As[2][16][136];
    __shared__ float Bs[2][16][64];

    const int t  = threadIdx.x;
    const int tx = t & 15;
    const int ty = t >> 4;

    const int arow = t >> 1;
    const int akq  = (t & 1) << 3;
    const float* Aptr = g_attn + (m0 + arow) * Esz + akq;
    const int be = t >> 4;
    const int bd = (t & 15) << 2;
    const float* Bptr = Wo + be * Esz + n0 + bd;

    float4 pa0 = *(const float4*)(Aptr);
    float4 pa1 = *(const float4*)(Aptr + 4);
    float4 pb  = *(const float4*)(Bptr);

    As[0][akq + 0][arow] = pa0.x;
    As[0][akq + 1][arow] = pa0.y;
    As[0][akq + 2][arow] = pa0.z;
    As[0][akq + 3][arow] = pa0.w;
    As[0][akq + 4][arow] = pa1.x;
    As[0][akq + 5][arow] = pa1.y;
    As[0][akq + 6][arow] = pa1.z;
    As[0][akq + 7][arow] = pa1.w;
    *(float4*)&Bs[0][be][bd] = pb;
    __syncthreads();

    float acc[8][4];
    #pragma unroll
    for (int i = 0; i < 8; i++)
        #pragma unroll
        for (int j = 0; j < 4; j++) acc[i][j] = 0.f;

    for (int k0 = 0; k0 < Esz; k0 += 16) {
        const int buf = (k0 >> 4) & 1;
        const bool more = (k0 + 16) < Esz;
        if (more) {
            pa0 = *(const float4*)(Aptr + k0 + 16);
            pa1 = *(const float4*)(Aptr + k0 + 20);
            pb  = *(const float4*)(Bptr + (k0 + 16) * Esz);
        }
        #pragma unroll
        for (int kk = 0; kk < 16; kk++) {
            float4 a0 = *(float4*)&As[buf][kk][ty * 8];
            float4 a1 = *(float4*)&As[buf][kk][ty * 8 + 4];
            float4 bv = *(float4*)&Bs[buf][kk][tx * 4];
            acc[0][0] += a0.x * bv.x; acc[0][1] += a0.x * bv.y; acc[0][2] += a0.x * bv.z; acc[0][3] += a0.x * bv.w;
            acc[1][0] += a0.y * bv.x; acc[1][1] += a0.y * bv.y; acc[1][2] += a0.y * bv.z; acc[1][3] += a0.y * bv.w;
            acc[2][0] += a0.z * bv.x; acc[2][1] += a0.z * bv.y; acc[2][2] += a0.z * bv.z; acc[2][3] += a0.z * bv.w;
            acc[3][0] += a0.w * bv.x; acc[3][1] += a0.w * bv.y; acc[3][2] += a0.w * bv.z; acc[3][3] += a0.w * bv.w;
            acc[4][0] += a1.x * bv.x; acc[4][1] += a1.x * bv.y; acc[4][2] += a1.x * bv.z; acc[4][3] += a1.x * bv.w;
            acc[5][0] += a1.y * bv.x; acc[5][1] += a1.y * bv.y; acc[5][2] += a1.y * bv.z; acc[5][3] += a1.y * bv.w;
            acc[6][0] += a1.z * bv.x; acc[6][1] += a1.z * bv.y; acc[6][2] += a1.z * bv.z; acc[6][3] += a1.z * bv.w;
            acc[7][0] += a1.w * bv.x; acc[7][1] += a1.w * bv.y; acc[7][2] += a1.w * bv.z; acc[7][3] += a1.w * bv.w;
        }
        if (more) {
            const int nb = buf ^ 1;
            As[nb][akq + 0][arow] = pa0.x;
            As[nb][akq + 1][arow] = pa0.y;
            As[nb][akq + 2][arow] = pa0.z;
            As[nb][akq + 3][arow] = pa0.w;
            As[nb][akq + 4][arow] = pa1.x;
            As[nb][akq + 5][arow] = pa1.y;
            As[nb][akq + 6][arow] = pa1.z;
            As[nb][akq + 7][arow] = pa1.w;
            *(float4*)&Bs[nb][be][bd] = pb;
        }
        __syncthreads();
    }

    float4 bb = *(const float4*)(bo + n0 + tx * 4);
    #pragma unroll
    for (int i = 0; i < 8; i++) {
        int mrow = m0 + ty * 8 + i;
        float4 w;
        w.x = acc[i][0] + bb.x;
        w.y = acc[i][1] + bb.y;
        w.z = acc[i][2] + bb.z;
        w.w = acc[i][3] + bb.w;
        *(float4*)(out + mrow * Esz + n0 + (tx << 2)) = w;
    }
}

// ---------------- launch ----------------
extern "C" void kernel_launch(void* const* d_in, const int* in_sizes, int n_in,
                              void* d_out, int out_size)
{
    const float* X  = (const float*)d_in[0];
    const float* Wq = (const float*)d_in[1];
    const float* bq = (const float*)d_in[2];
    const float* Wk = (const float*)d_in[3];
    const float* bk = (const float*)d_in[4];
    const float* Wv = (const float*)d_in[5];
    const float* bv = (const float*)d_in[6];
    const float* Wo = (const float*)d_in[7];
    const float* bo = (const float*)d_in[8];
    float* out = (float*)d_out;

    dim3 g1(Hsz, Msz / 128, 3);            // (12, 64, 3)
    qkv_gemm<<<g1, 256>>>(X, Wq, bq, Wk, bk, Wv, bv);

    dim3 g2(Ssz / 64, Bsz * Hsz);          // (16, 96)
    attn_kernel<<<g2, 128>>>();

    dim3 g3(Esz / 64, Msz / 128);          // (12, 64)
    oproj_gemm<<<g3, 256>>>(Wo, bo, out);
}

// round 4
// speedup vs baseline: 3.1955x; 1.6651x over previous
#include <cuda_runtime.h>
#include <cuda_bf16.h>

#define Bsz 8
#define Ssz 1024
#define Esz 768
#define Hsz 12
#define Dsz 64
#define Msz (Bsz*Ssz)   // 8192

// ---------------- scratch (device globals; no allocation) ----------------
__device__ float g_q[Bsz*Hsz*Ssz*Dsz];     // [B,H,S,D]
__device__ float g_k[Bsz*Hsz*Ssz*Dsz];
__device__ float g_v[Bsz*Hsz*Ssz*Dsz];
__device__ float g_attn[Bsz*Ssz*Esz];      // [B,S,E] concat-heads

// ---------------- tf32 helpers ----------------
__device__ __forceinline__ unsigned f2tf(float f) {
    unsigned u;
    asm("cvt.rna.tf32.f32 %0, %1;" : "=r"(u) : "f"(f));
    return u;
}
__device__ __forceinline__ void mma_tf32(float* c, const unsigned* a, unsigned b0, unsigned b1) {
    asm volatile(
        "mma.sync.aligned.m16n8k8.row.col.f32.tf32.tf32.f32 "
        "{%0,%1,%2,%3}, {%4,%5,%6,%7}, {%8,%9}, {%0,%1,%2,%3};"
        : "+f"(c[0]), "+f"(c[1]), "+f"(c[2]), "+f"(c[3])
        : "r"(a[0]), "r"(a[1]), "r"(a[2]), "r"(a[3]), "r"(b0), "r"(b1));
}

// shared GEMM tile constants
#define AST 17      // A smem stride ([m][k], k=16 + pad)
#define BST 72      // B smem stride ([k][n], n=64 + pad)

// ============================================================================
// QKV projection, tf32 MMA: C[128,64] tile per block, 8 warps, warp tile 32x32.
// grid (H, M/128, 3); z selects q/k/v. Double-buffered Kc=16 chunks.
// ============================================================================
__global__ __launch_bounds__(256) void qkv_mma(
    const float* __restrict__ X,
    const float* __restrict__ Wq, const float* __restrict__ bq,
    const float* __restrict__ Wk, const float* __restrict__ bk,
    const float* __restrict__ Wv, const float* __restrict__ bv)
{
    const int which = blockIdx.z;
    const float* W    = (which == 0) ? Wq : (which == 1 ? Wk : Wv);
    const float* bias = (which == 0) ? bq : (which == 1 ? bk : bv);
    float* OUT        = (which == 0) ? g_q : (which == 1 ? g_k : g_v);

    const int h  = blockIdx.x;
    const int m0 = blockIdx.y * 128;

    __shared__ unsigned As[2][128 * AST];
    __shared__ unsigned Bs[2][16 * BST];

    const int t    = threadIdx.x;
    const int warp = t >> 5;
    const int lane = t & 31;
    const int g    = lane >> 2;
    const int tg   = lane & 3;
    const int wm   = (warp & 3) * 32;      // warp m-base in tile
    const int wn   = (warp >> 2) * 32;     // warp n-base in tile

    // global load mapping
    const int ar = t >> 2;                 // A rows: ar and ar+64
    const int ac = (t & 3) << 2;
    const float* Aptr = X + (m0 + ar) * Esz + ac;
    const float* Wh   = W + h * (Esz * Dsz);
    const int bk_ = t >> 4;                // B k-row 0..15
    const int bn  = (t & 15) << 2;
    const float* Bptr = Wh + bk_ * Dsz + bn;

    // prologue: chunk 0
    float4 pa0 = *(const float4*)(Aptr);
    float4 pa1 = *(const float4*)(Aptr + 64 * Esz);
    float4 pb  = *(const float4*)(Bptr);
    {
        unsigned* A0 = &As[0][ar * AST + ac];
        A0[0] = f2tf(pa0.x); A0[1] = f2tf(pa0.y); A0[2] = f2tf(pa0.z); A0[3] = f2tf(pa0.w);
        unsigned* A1 = &As[0][(ar + 64) * AST + ac];
        A1[0] = f2tf(pa1.x); A1[1] = f2tf(pa1.y); A1[2] = f2tf(pa1.z); A1[3] = f2tf(pa1.w);
        uint4 ub;
        ub.x = f2tf(pb.x); ub.y = f2tf(pb.y); ub.z = f2tf(pb.z); ub.w = f2tf(pb.w);
        *(uint4*)&Bs[0][bk_ * BST + bn] = ub;
    }
    __syncthreads();

    float acc[2][4][4];
    #pragma unroll
    for (int mi = 0; mi < 2; mi++)
        #pragma unroll
        for (int ni = 0; ni < 4; ni++)
            #pragma unroll
            for (int j = 0; j < 4; j++) acc[mi][ni][j] = 0.f;

    for (int k0 = 0; k0 < Esz; k0 += 16) {
        const int buf = (k0 >> 4) & 1;
        const bool more = (k0 + 16) < Esz;
        if (more) {
            pa0 = *(const float4*)(Aptr + k0 + 16);
            pa1 = *(const float4*)(Aptr + 64 * Esz + k0 + 16);
            pb  = *(const float4*)(Bptr + (k0 + 16) * Dsz);
        }
        #pragma unroll
        for (int ks = 0; ks < 2; ks++) {
            unsigned a[2][4];
            #pragma unroll
            for (int mi = 0; mi < 2; mi++) {
                const int rbase = (wm + mi * 16 + g) * AST + ks * 8 + tg;
                a[mi][0] = As[buf][rbase];
                a[mi][1] = As[buf][rbase + 8 * AST];
                a[mi][2] = As[buf][rbase + 4];
                a[mi][3] = As[buf][rbase + 8 * AST + 4];
            }
            #pragma unroll
            for (int ni = 0; ni < 4; ni++) {
                unsigned b0 = Bs[buf][(ks * 8 + tg) * BST + wn + ni * 8 + g];
                unsigned b1 = Bs[buf][(ks * 8 + tg + 4) * BST + wn + ni * 8 + g];
                mma_tf32(acc[0][ni], a[0], b0, b1);
                mma_tf32(acc[1][ni], a[1], b0, b1);
            }
        }
        if (more) {
            const int nb = buf ^ 1;
            unsigned* A0 = &As[nb][ar * AST + ac];
            A0[0] = f2tf(pa0.x); A0[1] = f2tf(pa0.y); A0[2] = f2tf(pa0.z); A0[3] = f2tf(pa0.w);
            unsigned* A1 = &As[nb][(ar + 64) * AST + ac];
            A1[0] = f2tf(pa1.x); A1[1] = f2tf(pa1.y); A1[2] = f2tf(pa1.z); A1[3] = f2tf(pa1.w);
            uint4 ub;
            ub.x = f2tf(pb.x); ub.y = f2tf(pb.y); ub.z = f2tf(pb.z); ub.w = f2tf(pb.w);
            *(uint4*)&Bs[nb][bk_ * BST + bn] = ub;
        }
        __syncthreads();
    }

    // epilogue: bias + write [B,H,S,D]
    #pragma unroll
    for (int mi = 0; mi < 2; mi++) {
        const int row_lo = m0 + wm + mi * 16 + g;
        const int row_hi = row_lo + 8;
        const int blo = row_lo >> 10, slo = row_lo & 1023;
        const int bhi = row_hi >> 10, shi = row_hi & 1023;
        float* olo = OUT + (((blo * Hsz + h) << 10) + slo) * Dsz;
        float* ohi = OUT + (((bhi * Hsz + h) << 10) + shi) * Dsz;
        #pragma unroll
        for (int ni = 0; ni < 4; ni++) {
            const int col = wn + ni * 8 + 2 * tg;
            float2 bb = *(const float2*)(bias + h * Dsz + col);
            float2 wlo, whi;
            wlo.x = acc[mi][ni][0] + bb.x; wlo.y = acc[mi][ni][1] + bb.y;
            whi.x = acc[mi][ni][2] + bb.x; whi.y = acc[mi][ni][3] + bb.y;
            *(float2*)(olo + col) = wlo;
            *(float2*)(ohi + col) = whi;
        }
    }
}

// ============================================================================
// Output projection, tf32 MMA: same structure, B = Wo[768,768].
// grid (E/64, M/128).
// ============================================================================
__global__ __launch_bounds__(256) void oproj_mma(
    const float* __restrict__ Wo, const float* __restrict__ bo,
    float* __restrict__ out)
{
    const int n0 = blockIdx.x * 64;
    const int m0 = blockIdx.y * 128;

    __shared__ unsigned As[2][128 * AST];
    __shared__ unsigned Bs[2][16 * BST];

    const int t    = threadIdx.x;
    const int warp = t >> 5;
    const int lane = t & 31;
    const int g    = lane >> 2;
    const int tg   = lane & 3;
    const int wm   = (warp & 3) * 32;
    const int wn   = (warp >> 2) * 32;

    const int ar = t >> 2;
    const int ac = (t & 3) << 2;
    const float* Aptr = g_attn + (m0 + ar) * Esz + ac;
    const int bk_ = t >> 4;
    const int bn  = (t & 15) << 2;
    const float* Bptr = Wo + bk_ * Esz + n0 + bn;

    float4 pa0 = *(const float4*)(Aptr);
    float4 pa1 = *(const float4*)(Aptr + 64 * Esz);
    float4 pb  = *(const float4*)(Bptr);
    {
        unsigned* A0 = &As[0][ar * AST + ac];
        A0[0] = f2tf(pa0.x); A0[1] = f2tf(pa0.y); A0[2] = f2tf(pa0.z); A0[3] = f2tf(pa0.w);
        unsigned* A1 = &As[0][(ar + 64) * AST + ac];
        A1[0] = f2tf(pa1.x); A1[1] = f2tf(pa1.y); A1[2] = f2tf(pa1.z); A1[3] = f2tf(pa1.w);
        uint4 ub;
        ub.x = f2tf(pb.x); ub.y = f2tf(pb.y); ub.z = f2tf(pb.z); ub.w = f2tf(pb.w);
        *(uint4*)&Bs[0][bk_ * BST + bn] = ub;
    }
    __syncthreads();

    float acc[2][4][4];
    #pragma unroll
    for (int mi = 0; mi < 2; mi++)
        #pragma unroll
        for (int ni = 0; ni < 4; ni++)
            #pragma unroll
            for (int j = 0; j < 4; j++) acc[mi][ni][j] = 0.f;

    for (int k0 = 0; k0 < Esz; k0 += 16) {
        const int buf = (k0 >> 4) & 1;
        const bool more = (k0 + 16) < Esz;
        if (more) {
            pa0 = *(const float4*)(Aptr + k0 + 16);
            pa1 = *(const float4*)(Aptr + 64 * Esz + k0 + 16);
            pb  = *(const float4*)(Bptr + (k0 + 16) * Esz);
        }
        #pragma unroll
        for (int ks = 0; ks < 2; ks++) {
            unsigned a[2][4];
            #pragma unroll
            for (int mi = 0; mi < 2; mi++) {
                const int rbase = (wm + mi * 16 + g) * AST + ks * 8 + tg;
                a[mi][0] = As[buf][rbase];
                a[mi][1] = As[buf][rbase + 8 * AST];
                a[mi][2] = As[buf][rbase + 4];
                a[mi][3] = As[buf][rbase + 8 * AST + 4];
            }
            #pragma unroll
            for (int ni = 0; ni < 4; ni++) {
                unsigned b0 = Bs[buf][(ks * 8 + tg) * BST + wn + ni * 8 + g];
                unsigned b1 = Bs[buf][(ks * 8 + tg + 4) * BST + wn + ni * 8 + g];
                mma_tf32(acc[0][ni], a[0], b0, b1);
                mma_tf32(acc[1][ni], a[1], b0, b1);
            }
        }
        if (more) {
            const int nb = buf ^ 1;
            unsigned* A0 = &As[nb][ar * AST + ac];
            A0[0] = f2tf(pa0.x); A0[1] = f2tf(pa0.y); A0[2] = f2tf(pa0.z); A0[3] = f2tf(pa0.w);
            unsigned* A1 = &As[nb][(ar + 64) * AST + ac];
            A1[0] = f2tf(pa1.x); A1[1] = f2tf(pa1.y); A1[2] = f2tf(pa1.z); A1[3] = f2tf(pa1.w);
            uint4 ub;
            ub.x = f2tf(pb.x); ub.y = f2tf(pb.y); ub.z = f2tf(pb.z); ub.w = f2tf(pb.w);
            *(uint4*)&Bs[nb][bk_ * BST + bn] = ub;
        }
        __syncthreads();
    }

    #pragma unroll
    for (int mi = 0; mi < 2; mi++) {
        const int row_lo = m0 + wm + mi * 16 + g;
        float* olo = out + row_lo * Esz + n0;
        float* ohi = out + (row_lo + 8) * Esz + n0;
        #pragma unroll
        for (int ni = 0; ni < 4; ni++) {
            const int col = wn + ni * 8 + 2 * tg;
            float2 bb = *(const float2*)(bo + n0 + col);
            float2 wlo, whi;
            wlo.x = acc[mi][ni][0] + bb.x; wlo.y = acc[mi][ni][1] + bb.y;
            whi.x = acc[mi][ni][2] + bb.x; whi.y = acc[mi][ni][3] + bb.y;
            *(float2*)(olo + col) = wlo;
            *(float2*)(ohi + col) = whi;
        }
    }
}

// ============================================================================
// Flash attention with tf32 mma (unchanged from R3)
// ============================================================================
#define KST 68
#define VST 72

__global__ __launch_bounds__(128) void attn_kernel()
{
    __shared__ unsigned Ksm[64 * KST];
    __shared__ unsigned Vsm[64 * VST];

    const int bh = blockIdx.y;
    const int b = bh / Hsz, h = bh % Hsz;
    const int tid  = threadIdx.x;
    const int warp = tid >> 5;
    const int lane = tid & 31;
    const int g  = lane >> 2;
    const int tg = lane & 3;
    const int r0 = warp * 16;

    {
        const float4* Qg = (const float4*)(g_q + (bh * Ssz + blockIdx.x * 64) * Dsz);
        #pragma unroll
        for (int i = 0; i < 8; i++) {
            int idx = i * 128 + tid;
            int row = idx >> 4, c = (idx & 15) << 2;
            float4 qv = Qg[idx];
            uint4 u;
            u.x = f2tf(qv.x * 0.125f);
            u.y = f2tf(qv.y * 0.125f);
            u.z = f2tf(qv.z * 0.125f);
            u.w = f2tf(qv.w * 0.125f);
            *(uint4*)&Ksm[row * KST + c] = u;
        }
    }
    __syncthreads();

    unsigned qa[8][4];
    #pragma unroll
    for (int kk = 0; kk < 8; kk++) {
        qa[kk][0] = Ksm[(r0 + g) * KST + kk * 8 + tg];
        qa[kk][1] = Ksm[(r0 + g + 8) * KST + kk * 8 + tg];
        qa[kk][2] = Ksm[(r0 + g) * KST + kk * 8 + tg + 4];
        qa[kk][3] = Ksm[(r0 + g + 8) * KST + kk * 8 + tg + 4];
    }
    __syncthreads();

    float o[8][4];
    #pragma unroll
    for (int nf = 0; nf < 8; nf++)
        #pragma unroll
        for (int j = 0; j < 4; j++) o[nf][j] = 0.f;
    float m_lo = -1e30f, m_hi = -1e30f, l_lo = 0.f, l_hi = 0.f;

    const float4* Kg0 = (const float4*)(g_k + bh * (Ssz * Dsz));
    const float4* Vg0 = (const float4*)(g_v + bh * (Ssz * Dsz));

    for (int kb = 0; kb < Ssz / 64; kb++) {
        const float4* Kg = Kg0 + kb * 1024;
        const float4* Vg = Vg0 + kb * 1024;
        #pragma unroll
        for (int i = 0; i < 8; i++) {
            int idx = i * 128 + tid;
            int row = idx >> 4, c = (idx & 15) << 2;
            float4 kv = Kg[idx];
            uint4 uk;
            uk.x = f2tf(kv.x); uk.y = f2tf(kv.y); uk.z = f2tf(kv.z); uk.w = f2tf(kv.w);
            *(uint4*)&Ksm[row * KST + c] = uk;
            float4 vv = Vg[idx];
            uint4 uv;
            uv.x = f2tf(vv.x); uv.y = f2tf(vv.y); uv.z = f2tf(vv.z); uv.w = f2tf(vv.w);
            *(uint4*)&Vsm[row * VST + c] = uv;
        }
        __syncthreads();

        float s[8][4];
        #pragma unroll
        for (int nf = 0; nf < 8; nf++)
            #pragma unroll
            for (int j = 0; j < 4; j++) s[nf][j] = 0.f;

        #pragma unroll
        for (int nf = 0; nf < 8; nf++) {
            const int jrow = (nf * 8 + g) * KST;
            #pragma unroll
            for (int kk = 0; kk < 8; kk++) {
                unsigned b0 = Ksm[jrow + kk * 8 + tg];
                unsigned b1 = Ksm[jrow + kk * 8 + tg + 4];
                mma_tf32(s[nf], qa[kk], b0, b1);
            }
        }
        __syncthreads();

        float tmax_lo = -1e30f, tmax_hi = -1e30f;
        #pragma unroll
        for (int nf = 0; nf < 8; nf++) {
            tmax_lo = fmaxf(tmax_lo, fmaxf(s[nf][0], s[nf][1]));
            tmax_hi = fmaxf(tmax_hi, fmaxf(s[nf][2], s[nf][3]));
        }
        tmax_lo = fmaxf(tmax_lo, __shfl_xor_sync(0xffffffffu, tmax_lo, 1));
        tmax_lo = fmaxf(tmax_lo, __shfl_xor_sync(0xffffffffu, tmax_lo, 2));
        tmax_hi = fmaxf(tmax_hi, __shfl_xor_sync(0xffffffffu, tmax_hi, 1));
        tmax_hi = fmaxf(tmax_hi, __shfl_xor_sync(0xffffffffu, tmax_hi, 2));

        float mn_lo = fmaxf(m_lo, tmax_lo);
        float mn_hi = fmaxf(m_hi, tmax_hi);
        float a_lo = __expf(m_lo - mn_lo);
        float a_hi = __expf(m_hi - mn_hi);

        float sum_lo = 0.f, sum_hi = 0.f;
        #pragma unroll
        for (int nf = 0; nf < 8; nf++) {
            float p0 = __expf(s[nf][0] - mn_lo);
            float p1 = __expf(s[nf][1] - mn_lo);
            float p2 = __expf(s[nf][2] - mn_hi);
            float p3 = __expf(s[nf][3] - mn_hi);
            sum_lo += p0 + p1;
            sum_hi += p2 + p3;
            uint2 plo, phi;
            plo.x = f2tf(p0); plo.y = f2tf(p1);
            phi.x = f2tf(p2); phi.y = f2tf(p3);
            *(uint2*)&Ksm[(r0 + g) * KST + nf * 8 + 2 * tg]     = plo;
            *(uint2*)&Ksm[(r0 + g + 8) * KST + nf * 8 + 2 * tg] = phi;
            o[nf][0] *= a_lo; o[nf][1] *= a_lo;
            o[nf][2] *= a_hi; o[nf][3] *= a_hi;
        }
        sum_lo += __shfl_xor_sync(0xffffffffu, sum_lo, 1);
        sum_lo += __shfl_xor_sync(0xffffffffu, sum_lo, 2);
        sum_hi += __shfl_xor_sync(0xffffffffu, sum_hi, 1);
        sum_hi += __shfl_xor_sync(0xffffffffu, sum_hi, 2);
        l_lo = l_lo * a_lo + sum_lo;
        l_hi = l_hi * a_hi + sum_hi;
        m_lo = mn_lo; m_hi = mn_hi;
        __syncwarp();

        #pragma unroll
        for (int kk = 0; kk < 8; kk++) {
            unsigned pa[4];
            pa[0] = Ksm[(r0 + g) * KST + kk * 8 + tg];
            pa[1] = Ksm[(r0 + g + 8) * KST + kk * 8 + tg];
            pa[2] = Ksm[(r0 + g) * KST + kk * 8 + tg + 4];
            pa[3] = Ksm[(r0 + g + 8) * KST + kk * 8 + tg + 4];
            #pragma unroll
            for (int nf = 0; nf < 8; nf++) {
                unsigned b0 = Vsm[(kk * 8 + tg) * VST + nf * 8 + g];
                unsigned b1 = Vsm[(kk * 8 + tg + 4) * VST + nf * 8 + g];
                mma_tf32(o[nf], pa, b0, b1);
            }
        }
        __syncthreads();
    }

    float inv_lo = 1.f / l_lo;
    float inv_hi = 1.f / l_hi;
    const int qrow_lo = blockIdx.x * 64 + r0 + g;
    float* out_lo = g_attn + (b * Ssz + qrow_lo) * Esz + h * Dsz;
    float* out_hi = out_lo + 8 * Esz;
    #pragma unroll
    for (int nf = 0; nf < 8; nf++) {
        int col = nf * 8 + 2 * tg;
        float2 wlo, whi;
        wlo.x = o[nf][0] * inv_lo; wlo.y = o[nf][1] * inv_lo;
        whi.x = o[nf][2] * inv_hi; whi.y = o[nf][3] * inv_hi;
        *(float2*)(out_lo + col) = wlo;
        *(float2*)(out_hi + col) = whi;
    }
}

// ---------------- launch ----------------
extern "C" void kernel_launch(void* const* d_in, const int* in_sizes, int n_in,
                              void* d_out, int out_size)
{
    const float* X  = (const float*)d_in[0];
    const float* Wq = (const float*)d_in[1];
    const float* bq = (const float*)d_in[2];
    const float* Wk = (const float*)d_in[3];
    const float* bk = (const float*)d_in[4];
    const float* Wv = (const float*)d_in[5];
    const float* bv = (const float*)d_in[6];
    const float* Wo = (const float*)d_in[7];
    const float* bo = (const float*)d_in[8];
    float* out = (float*)d_out;

    dim3 g1(Hsz, Msz / 128, 3);            // (12, 64, 3)
    qkv_mma<<<g1, 256>>>(X, Wq, bq, Wk, bk, Wv, bv);

    dim3 g2(Ssz / 64, Bsz * Hsz);          // (16, 96)
    attn_kernel<<<g2, 128>>>();

    dim3 g3(Esz / 64, Msz / 128);          // (12, 64)
    oproj_mma<<<g3, 256>>>(Wo, bo, out);
}

// round 5
// speedup vs baseline: 4.2339x; 1.3250x over previous
#include <cuda_runtime.h>
#include <cuda_bf16.h>

#define Bsz 8
#define Ssz 1024
#define Esz 768
#define Hsz 12
#define Dsz 64
#define Msz (Bsz*Ssz)   // 8192

// ---------------- scratch (device globals; no allocation) ----------------
__device__ float g_q[Bsz*Hsz*Ssz*Dsz];     // [B,H,S,D]
__device__ float g_k[Bsz*Hsz*Ssz*Dsz];
__device__ float g_v[Bsz*Hsz*Ssz*Dsz];
__device__ float g_attn[Bsz*Ssz*Esz];      // [B,S,E] concat-heads

// ---------------- helpers ----------------
__device__ __forceinline__ unsigned f2tf(float f) {
    unsigned u;
    asm("cvt.rna.tf32.f32 %0, %1;" : "=r"(u) : "f"(f));
    return u;
}
__device__ __forceinline__ void mma_tf32(float* c, const unsigned* a, unsigned b0, unsigned b1) {
    asm volatile(
        "mma.sync.aligned.m16n8k8.row.col.f32.tf32.tf32.f32 "
        "{%0,%1,%2,%3}, {%4,%5,%6,%7}, {%8,%9}, {%0,%1,%2,%3};"
        : "+f"(c[0]), "+f"(c[1]), "+f"(c[2]), "+f"(c[3])
        : "r"(a[0]), "r"(a[1]), "r"(a[2]), "r"(a[3]), "r"(b0), "r"(b1));
}
__device__ __forceinline__ void ldsm_x4(unsigned& r0, unsigned& r1, unsigned& r2, unsigned& r3,
                                        unsigned saddr) {
    asm volatile("ldmatrix.sync.aligned.m8n8.x4.shared.b16 {%0,%1,%2,%3}, [%4];"
        : "=r"(r0), "=r"(r1), "=r"(r2), "=r"(r3) : "r"(saddr));
}

// GEMM tile constants: block 128x128, Kc=16, 8 warps (2m x 4n), warp 64x32
#define AST 20      // A smem stride words ([m][k]): rows 80B, 16B-aligned, LDSM conflict-free
#define BST 136     // B smem stride words ([k][n]): frag banks 8*tg+g bijective

// ============================================================================
// QKV projection, tf32 MMA, ldmatrix A-frags. Block = 128 M x 128 N (2 heads).
// grid (Hsz/2, Msz/128, 3).
// ============================================================================
__global__ __launch_bounds__(256) void qkv_mma(
    const float* __restrict__ X,
    const float* __restrict__ Wq, const float* __restrict__ bq,
    const float* __restrict__ Wk, const float* __restrict__ bk,
    const float* __restrict__ Wv, const float* __restrict__ bv)
{
    const int which = blockIdx.z;
    const float* W    = (which == 0) ? Wq : (which == 1 ? Wk : Wv);
    const float* bias = (which == 0) ? bq : (which == 1 ? bk : bv);
    float* OUT        = (which == 0) ? g_q : (which == 1 ? g_k : g_v);

    const int h0 = blockIdx.x * 2;
    const int m0 = blockIdx.y * 128;

    __shared__ unsigned As[2][128 * AST];  // 20.0 KB
    __shared__ unsigned Bs[2][16 * BST];   // 17.0 KB

    const int t    = threadIdx.x;
    const int warp = t >> 5;
    const int lane = t & 31;
    const int g    = lane >> 2;
    const int tg   = lane & 3;
    const int wm   = (warp & 1) * 64;
    const int wn   = (warp >> 1) * 32;

    // LDSM lane offsets for A frags
    const unsigned a_lane = (((lane >> 3) & 1) * 8 + (lane & 7)) * AST + (lane >> 4) * 4;
    unsigned as_base0 = (unsigned)__cvta_generic_to_shared(&As[0][0]);
    unsigned as_base1 = (unsigned)__cvta_generic_to_shared(&As[1][0]);

    // global A mapping: idx in {t, t+256}: row = idx>>2, c4 = idx&3
    const int ar0 = t >> 2, ac = (t & 3) << 2;
    const float* Aptr = X + (m0 + ar0) * Esz + ac;          // second row: +64 rows
    // global B mapping: idx in {t, t+256}: bk = idx>>5, n = (idx&31)*4
    const int bk0 = t >> 5, bn = (t & 31) << 2;
    const int bh  = h0 + (bn >> 6), bd = bn & 63;
    const float* Bptr = W + bh * (Esz * Dsz) + bk0 * Dsz + bd;   // second: +8 k-rows

    float4 pa0 = *(const float4*)(Aptr);
    float4 pa1 = *(const float4*)(Aptr + 64 * Esz);
    float4 pb0 = *(const float4*)(Bptr);
    float4 pb1 = *(const float4*)(Bptr + 8 * Dsz);
    {
        uint4 u;
        u.x = f2tf(pa0.x); u.y = f2tf(pa0.y); u.z = f2tf(pa0.z); u.w = f2tf(pa0.w);
        *(uint4*)&As[0][ar0 * AST + ac] = u;
        u.x = f2tf(pa1.x); u.y = f2tf(pa1.y); u.z = f2tf(pa1.z); u.w = f2tf(pa1.w);
        *(uint4*)&As[0][(ar0 + 64) * AST + ac] = u;
        u.x = f2tf(pb0.x); u.y = f2tf(pb0.y); u.z = f2tf(pb0.z); u.w = f2tf(pb0.w);
        *(uint4*)&Bs[0][bk0 * BST + bn] = u;
        u.x = f2tf(pb1.x); u.y = f2tf(pb1.y); u.z = f2tf(pb1.z); u.w = f2tf(pb1.w);
        *(uint4*)&Bs[0][(bk0 + 8) * BST + bn] = u;
    }
    __syncthreads();

    float acc[4][4][4];
    #pragma unroll
    for (int mi = 0; mi < 4; mi++)
        #pragma unroll
        for (int ni = 0; ni < 4; ni++)
            #pragma unroll
            for (int j = 0; j < 4; j++) acc[mi][ni][j] = 0.f;

    for (int k0 = 0; k0 < Esz; k0 += 16) {
        const int buf = (k0 >> 4) & 1;
        const unsigned as_base = buf ? as_base1 : as_base0;
        const bool more = (k0 + 16) < Esz;
        if (more) {
            pa0 = *(const float4*)(Aptr + k0 + 16);
            pa1 = *(const float4*)(Aptr + 64 * Esz + k0 + 16);
            pb0 = *(const float4*)(Bptr + (k0 + 16) * Dsz);
            pb1 = *(const float4*)(Bptr + (k0 + 24) * Dsz);
        }
        #pragma unroll
        for (int ks = 0; ks < 2; ks++) {
            unsigned a[4][4];
            #pragma unroll
            for (int mi = 0; mi < 4; mi++) {
                unsigned addr = as_base + 4 * ((wm + mi * 16) * AST + ks * 8 + a_lane);
                ldsm_x4(a[mi][0], a[mi][1], a[mi][2], a[mi][3], addr);
            }
            #pragma unroll
            for (int ni = 0; ni < 4; ni++) {
                unsigned b0 = Bs[buf][(ks * 8 + tg) * BST + wn + ni * 8 + g];
                unsigned b1 = Bs[buf][(ks * 8 + tg + 4) * BST + wn + ni * 8 + g];
                #pragma unroll
                for (int mi = 0; mi < 4; mi++)
                    mma_tf32(acc[mi][ni], a[mi], b0, b1);
            }
        }
        if (more) {
            const int nb = buf ^ 1;
            uint4 u;
            u.x = f2tf(pa0.x); u.y = f2tf(pa0.y); u.z = f2tf(pa0.z); u.w = f2tf(pa0.w);
            *(uint4*)&As[nb][ar0 * AST + ac] = u;
            u.x = f2tf(pa1.x); u.y = f2tf(pa1.y); u.z = f2tf(pa1.z); u.w = f2tf(pa1.w);
            *(uint4*)&As[nb][(ar0 + 64) * AST + ac] = u;
            u.x = f2tf(pb0.x); u.y = f2tf(pb0.y); u.z = f2tf(pb0.z); u.w = f2tf(pb0.w);
            *(uint4*)&Bs[nb][bk0 * BST + bn] = u;
            u.x = f2tf(pb1.x); u.y = f2tf(pb1.y); u.z = f2tf(pb1.z); u.w = f2tf(pb1.w);
            *(uint4*)&Bs[nb][(bk0 + 8) * BST + bn] = u;
        }
        __syncthreads();
    }

    // epilogue: bias + write [B,H,S,D]
    #pragma unroll
    for (int mi = 0; mi < 4; mi++) {
        const int row_lo = m0 + wm + mi * 16 + g;
        const int row_hi = row_lo + 8;
        const int blo = row_lo >> 10, slo = row_lo & 1023;
        const int bhi = row_hi >> 10, shi = row_hi & 1023;
        #pragma unroll
        for (int ni = 0; ni < 4; ni++) {
            const int col  = wn + ni * 8 + 2 * tg;
            const int head = h0 + (col >> 6);
            const int d    = col & 63;
            float2 bb = *(const float2*)(bias + head * Dsz + d);
            float* olo = OUT + (((blo * Hsz + head) << 10) + slo) * Dsz + d;
            float* ohi = OUT + (((bhi * Hsz + head) << 10) + shi) * Dsz + d;
            float2 wlo, whi;
            wlo.x = acc[mi][ni][0] + bb.x; wlo.y = acc[mi][ni][1] + bb.y;
            whi.x = acc[mi][ni][2] + bb.x; whi.y = acc[mi][ni][3] + bb.y;
            *(float2*)olo = wlo;
            *(float2*)ohi = whi;
        }
    }
}

// ============================================================================
// Output projection: identical structure, B = Wo[768,768]. grid (6, 64).
// ============================================================================
__global__ __launch_bounds__(256) void oproj_mma(
    const float* __restrict__ Wo, const float* __restrict__ bo,
    float* __restrict__ out)
{
    const int n0 = blockIdx.x * 128;
    const int m0 = blockIdx.y * 128;

    __shared__ unsigned As[2][128 * AST];
    __shared__ unsigned Bs[2][16 * BST];

    const int t    = threadIdx.x;
    const int warp = t >> 5;
    const int lane = t & 31;
    const int g    = lane >> 2;
    const int tg   = lane & 3;
    const int wm   = (warp & 1) * 64;
    const int wn   = (warp >> 1) * 32;

    const unsigned a_lane = (((lane >> 3) & 1) * 8 + (lane & 7)) * AST + (lane >> 4) * 4;
    unsigned as_base0 = (unsigned)__cvta_generic_to_shared(&As[0][0]);
    unsigned as_base1 = (unsigned)__cvta_generic_to_shared(&As[1][0]);

    const int ar0 = t >> 2, ac = (t & 3) << 2;
    const float* Aptr = g_attn + (m0 + ar0) * Esz + ac;
    const int bk0 = t >> 5, bn = (t & 31) << 2;
    const float* Bptr = Wo + bk0 * Esz + n0 + bn;

    float4 pa0 = *(const float4*)(Aptr);
    float4 pa1 = *(const float4*)(Aptr + 64 * Esz);
    float4 pb0 = *(const float4*)(Bptr);
    float4 pb1 = *(const float4*)(Bptr + 8 * Esz);
    {
        uint4 u;
        u.x = f2tf(pa0.x); u.y = f2tf(pa0.y); u.z = f2tf(pa0.z); u.w = f2tf(pa0.w);
        *(uint4*)&As[0][ar0 * AST + ac] = u;
        u.x = f2tf(pa1.x); u.y = f2tf(pa1.y); u.z = f2tf(pa1.z); u.w = f2tf(pa1.w);
        *(uint4*)&As[0][(ar0 + 64) * AST + ac] = u;
        u.x = f2tf(pb0.x); u.y = f2tf(pb0.y); u.z = f2tf(pb0.z); u.w = f2tf(pb0.w);
        *(uint4*)&Bs[0][bk0 * BST + bn] = u;
        u.x = f2tf(pb1.x); u.y = f2tf(pb1.y); u.z = f2tf(pb1.z); u.w = f2tf(pb1.w);
        *(uint4*)&Bs[0][(bk0 + 8) * BST + bn] = u;
    }
    __syncthreads();

    float acc[4][4][4];
    #pragma unroll
    for (int mi = 0; mi < 4; mi++)
        #pragma unroll
        for (int ni = 0; ni < 4; ni++)
            #pragma unroll
            for (int j = 0; j < 4; j++) acc[mi][ni][j] = 0.f;

    for (int k0 = 0; k0 < Esz; k0 += 16) {
        const int buf = (k0 >> 4) & 1;
        const unsigned as_base = buf ? as_base1 : as_base0;
        const bool more = (k0 + 16) < Esz;
        if (more) {
            pa0 = *(const float4*)(Aptr + k0 + 16);
            pa1 = *(const float4*)(Aptr + 64 * Esz + k0 + 16);
            pb0 = *(const float4*)(Bptr + (k0 + 16) * Esz);
            pb1 = *(const float4*)(Bptr + (k0 + 24) * Esz);
        }
        #pragma unroll
        for (int ks = 0; ks < 2; ks++) {
            unsigned a[4][4];
            #pragma unroll
            for (int mi = 0; mi < 4; mi++) {
                unsigned addr = as_base + 4 * ((wm + mi * 16) * AST + ks * 8 + a_lane);
                ldsm_x4(a[mi][0], a[mi][1], a[mi][2], a[mi][3], addr);
            }
            #pragma unroll
            for (int ni = 0; ni < 4; ni++) {
                unsigned b0 = Bs[buf][(ks * 8 + tg) * BST + wn + ni * 8 + g];
                unsigned b1 = Bs[buf][(ks * 8 + tg + 4) * BST + wn + ni * 8 + g];
                #pragma unroll
                for (int mi = 0; mi < 4; mi++)
                    mma_tf32(acc[mi][ni], a[mi], b0, b1);
            }
        }
        if (more) {
            const int nb = buf ^ 1;
            uint4 u;
            u.x = f2tf(pa0.x); u.y = f2tf(pa0.y); u.z = f2tf(pa0.z); u.w = f2tf(pa0.w);
            *(uint4*)&As[nb][ar0 * AST + ac] = u;
            u.x = f2tf(pa1.x); u.y = f2tf(pa1.y); u.z = f2tf(pa1.z); u.w = f2tf(pa1.w);
            *(uint4*)&As[nb][(ar0 + 64) * AST + ac] = u;
            u.x = f2tf(pb0.x); u.y = f2tf(pb0.y); u.z = f2tf(pb0.z); u.w = f2tf(pb0.w);
            *(uint4*)&Bs[nb][bk0 * BST + bn] = u;
            u.x = f2tf(pb1.x); u.y = f2tf(pb1.y); u.z = f2tf(pb1.z); u.w = f2tf(pb1.w);
            *(uint4*)&Bs[nb][(bk0 + 8) * BST + bn] = u;
        }
        __syncthreads();
    }

    #pragma unroll
    for (int mi = 0; mi < 4; mi++) {
        const int row_lo = m0 + wm + mi * 16 + g;
        float* olo = out + row_lo * Esz + n0;
        float* ohi = out + (row_lo + 8) * Esz + n0;
        #pragma unroll
        for (int ni = 0; ni < 4; ni++) {
            const int col = wn + ni * 8 + 2 * tg;
            float2 bb = *(const float2*)(bo + n0 + col);
            float2 wlo, whi;
            wlo.x = acc[mi][ni][0] + bb.x; wlo.y = acc[mi][ni][1] + bb.y;
            whi.x = acc[mi][ni][2] + bb.x; whi.y = acc[mi][ni][3] + bb.y;
            *(float2*)(olo + col) = wlo;
            *(float2*)(ohi + col) = whi;
        }
    }
}

// ============================================================================
// Flash attention (tf32 mma) — K-frags and P-frags now via ldmatrix.
// ============================================================================
#define KST 68      // 272B rows: 16B-aligned; LDSM row banks (r mod 8) distinct
#define VST 72

__global__ __launch_bounds__(128) void attn_kernel()
{
    __shared__ unsigned Ksm[64 * KST];     // K tile [n][k] -> reused as P [m][k]
    __shared__ unsigned Vsm[64 * VST];     // V tile [k][d]

    const int bh = blockIdx.y;
    const int b = bh / Hsz, h = bh % Hsz;
    const int tid  = threadIdx.x;
    const int warp = tid >> 5;
    const int lane = tid & 31;
    const int g  = lane >> 2;
    const int tg = lane & 3;
    const int r0 = warp * 16;

    const unsigned ks_base = (unsigned)__cvta_generic_to_shared(Ksm);
    // K-frag LDSM lane offset: row (lane&7), colgroup (lane>>3)*4
    const unsigned kf_lane = (lane & 7) * KST + (lane >> 3) * 4;
    // P-frag (A-op) LDSM lane offset
    const unsigned pf_lane = (((lane >> 3) & 1) * 8 + (lane & 7)) * KST + (lane >> 4) * 4;

    // ---- stage Q (scaled, tf32) into Ksm, extract A-frags ----
    {
        const float4* Qg = (const float4*)(g_q + (bh * Ssz + blockIdx.x * 64) * Dsz);
        #pragma unroll
        for (int i = 0; i < 8; i++) {
            int idx = i * 128 + tid;
            int row = idx >> 4, c = (idx & 15) << 2;
            float4 qv = Qg[idx];
            uint4 u;
            u.x = f2tf(qv.x * 0.125f);
            u.y = f2tf(qv.y * 0.125f);
            u.z = f2tf(qv.z * 0.125f);
            u.w = f2tf(qv.w * 0.125f);
            *(uint4*)&Ksm[row * KST + c] = u;
        }
    }
    __syncthreads();

    unsigned qa[8][4];
    #pragma unroll
    for (int kk = 0; kk < 8; kk++) {
        unsigned addr = ks_base + 4 * (r0 * KST + kk * 8 + pf_lane);
        ldsm_x4(qa[kk][0], qa[kk][1], qa[kk][2], qa[kk][3], addr);
    }
    __syncthreads();

    float o[8][4];
    #pragma unroll
    for (int nf = 0; nf < 8; nf++)
        #pragma unroll
        for (int j = 0; j < 4; j++) o[nf][j] = 0.f;
    float m_lo = -1e30f, m_hi = -1e30f, l_lo = 0.f, l_hi = 0.f;

    const float4* Kg0 = (const float4*)(g_k + bh * (Ssz * Dsz));
    const float4* Vg0 = (const float4*)(g_v + bh * (Ssz * Dsz));

    for (int kb = 0; kb < Ssz / 64; kb++) {
        const float4* Kg = Kg0 + kb * 1024;
        const float4* Vg = Vg0 + kb * 1024;
        #pragma unroll
        for (int i = 0; i < 8; i++) {
            int idx = i * 128 + tid;
            int row = idx >> 4, c = (idx & 15) << 2;
            float4 kv = Kg[idx];
            uint4 uk;
            uk.x = f2tf(kv.x); uk.y = f2tf(kv.y); uk.z = f2tf(kv.z); uk.w = f2tf(kv.w);
            *(uint4*)&Ksm[row * KST + c] = uk;
            float4 vv = Vg[idx];
            uint4 uv;
            uv.x = f2tf(vv.x); uv.y = f2tf(vv.y); uv.z = f2tf(vv.z); uv.w = f2tf(vv.w);
            *(uint4*)&Vsm[row * VST + c] = uv;
        }
        __syncthreads();

        // ---- S = Q K^T : K-frags via ldmatrix (each x4 covers 2 kk) ----
        float s[8][4];
        #pragma unroll
        for (int nf = 0; nf < 8; nf++)
            #pragma unroll
            for (int j = 0; j < 4; j++) s[nf][j] = 0.f;

        #pragma unroll
        for (int nf = 0; nf < 8; nf++) {
            #pragma unroll
            for (int p = 0; p < 4; p++) {
                unsigned kb0, kb1, kb2, kb3;
                unsigned addr = ks_base + 4 * ((nf * 8) * KST + p * 16 + kf_lane);
                ldsm_x4(kb0, kb1, kb2, kb3, addr);
                mma_tf32(s[nf], qa[2 * p],     kb0, kb1);
                mma_tf32(s[nf], qa[2 * p + 1], kb2, kb3);
            }
        }
        __syncthreads();

        // ---- online softmax ----
        float tmax_lo = -1e30f, tmax_hi = -1e30f;
        #pragma unroll
        for (int nf = 0; nf < 8; nf++) {
            tmax_lo = fmaxf(tmax_lo, fmaxf(s[nf][0], s[nf][1]));
            tmax_hi = fmaxf(tmax_hi, fmaxf(s[nf][2], s[nf][3]));
        }
        tmax_lo = fmaxf(tmax_lo, __shfl_xor_sync(0xffffffffu, tmax_lo, 1));
        tmax_lo = fmaxf(tmax_lo, __shfl_xor_sync(0xffffffffu, tmax_lo, 2));
        tmax_hi = fmaxf(tmax_hi, __shfl_xor_sync(0xffffffffu, tmax_hi, 1));
        tmax_hi = fmaxf(tmax_hi, __shfl_xor_sync(0xffffffffu, tmax_hi, 2));

        float mn_lo = fmaxf(m_lo, tmax_lo);
        float mn_hi = fmaxf(m_hi, tmax_hi);
        float a_lo = __expf(m_lo - mn_lo);
        float a_hi = __expf(m_hi - mn_hi);

        float sum_lo = 0.f, sum_hi = 0.f;
        #pragma unroll
        for (int nf = 0; nf < 8; nf++) {
            float p0 = __expf(s[nf][0] - mn_lo);
            float p1 = __expf(s[nf][1] - mn_lo);
            float p2 = __expf(s[nf][2] - mn_hi);
            float p3 = __expf(s[nf][3] - mn_hi);
            sum_lo += p0 + p1;
            sum_hi += p2 + p3;
            uint2 plo, phi;
            plo.x = f2tf(p0); plo.y = f2tf(p1);
            phi.x = f2tf(p2); phi.y = f2tf(p3);
            *(uint2*)&Ksm[(r0 + g) * KST + nf * 8 + 2 * tg]     = plo;
            *(uint2*)&Ksm[(r0 + g + 8) * KST + nf * 8 + 2 * tg] = phi;
            o[nf][0] *= a_lo; o[nf][1] *= a_lo;
            o[nf][2] *= a_hi; o[nf][3] *= a_hi;
        }
        sum_lo += __shfl_xor_sync(0xffffffffu, sum_lo, 1);
        sum_lo += __shfl_xor_sync(0xffffffffu, sum_lo, 2);
        sum_hi += __shfl_xor_sync(0xffffffffu, sum_hi, 1);
        sum_hi += __shfl_xor_sync(0xffffffffu, sum_hi, 2);
        l_lo = l_lo * a_lo + sum_lo;
        l_hi = l_hi * a_hi + sum_hi;
        m_lo = mn_lo; m_hi = mn_hi;
        __syncwarp();                      // P visible within warp

        // ---- O += P V : P-frags via ldmatrix, V scalar (conflict-free) ----
        #pragma unroll
        for (int kk = 0; kk < 8; kk++) {
            unsigned pa[4];
            unsigned addr = ks_base + 4 * (r0 * KST + kk * 8 + pf_lane);
            ldsm_x4(pa[0], pa[1], pa[2], pa[3], addr);
            #pragma unroll
            for (int nf = 0; nf < 8; nf++) {
                unsigned b0 = Vsm[(kk * 8 + tg) * VST + nf * 8 + g];
                unsigned b1 = Vsm[(kk * 8 + tg + 4) * VST + nf * 8 + g];
                mma_tf32(o[nf], pa, b0, b1);
            }
        }
        __syncthreads();
    }

    float inv_lo = 1.f / l_lo;
    float inv_hi = 1.f / l_hi;
    const int qrow_lo = blockIdx.x * 64 + r0 + g;
    float* out_lo = g_attn + (b * Ssz + qrow_lo) * Esz + h * Dsz;
    float* out_hi = out_lo + 8 * Esz;
    #pragma unroll
    for (int nf = 0; nf < 8; nf++) {
        int col = nf * 8 + 2 * tg;
        float2 wlo, whi;
        wlo.x = o[nf][0] * inv_lo; wlo.y = o[nf][1] * inv_lo;
        whi.x = o[nf][2] * inv_hi; whi.y = o[nf][3] * inv_hi;
        *(float2*)(out_lo + col) = wlo;
        *(float2*)(out_hi + col) = whi;
    }
}

// ---------------- launch ----------------
extern "C" void kernel_launch(void* const* d_in, const int* in_sizes, int n_in,
                              void* d_out, int out_size)
{
    const float* X  = (const float*)d_in[0];
    const float* Wq = (const float*)d_in[1];
    const float* bq = (const float*)d_in[2];
    const float* Wk = (const float*)d_in[3];
    const float* bk = (const float*)d_in[4];
    const float* Wv = (const float*)d_in[5];
    const float* bv = (const float*)d_in[6];
    const float* Wo = (const float*)d_in[7];
    const float* bo = (const float*)d_in[8];
    float* out = (float*)d_out;

    dim3 g1(Hsz / 2, Msz / 128, 3);        // (6, 64, 3)
    qkv_mma<<<g1, 256>>>(X, Wq, bq, Wk, bk, Wv, bv);

    dim3 g2(Ssz / 64, Bsz * Hsz);          // (16, 96)
    attn_kernel<<<g2, 128>>>();

    dim3 g3(Esz / 128, Msz / 128);         // (6, 64)
    oproj_mma<<<g3, 256>>>(Wo, bo, out);
}